// round 5
// baseline (speedup 1.0000x reference)
#include <cuda_runtime.h>
#include <math.h>

#define ND   768
#define NB   8
#define NCH  3
#define NMIX 5
#define NS   10
#define HH   10
#define PI2f 6.28318530717958647692f
#define ZITTERf 1e-4f
#define NPLANE (NB*NCH*NMIX)          // 120
#define LOG2Ef 1.4426950408889634f

__device__ float    g_feat[NPLANE * ND];   // zero-init; kA atomics; k34 reads then re-zeroes
__device__ float    g_hmean[NB * NCH * HH];
__device__ float    g_w[NB * NCH * NMIX];
__device__ unsigned g_ctr;                 // zero-init; k34 last-block counter (self-resetting)

__device__ __forceinline__ float ex2(float x) {
    float y; asm("ex2.approx.ftz.f32 %0, %1;" : "=f"(y) : "f"(x)); return y;
}

// ---------------------------------------------------------------------------
// Kernel A: feature[bc,m,i] = sum_j K_m(i,j)*yc[j], trig-separated:
//   K = exp2(B*d^2) * (cI*cJ + sI*sJ);  cJ*yj, sJ*yj precomputed per tile.
// Full grid (no symmetry). Thread: i = t>>2 (one row), jq = t&3 (16 j's).
// Per (pair,m): 1 MUFU + 3 FMA.
// ---------------------------------------------------------------------------
__global__ void __launch_bounds__(256) kA_feat(const float* __restrict__ xc,
                                               const float* __restrict__ yc,
                                               const float* __restrict__ mu,
                                               const float* __restrict__ inv_std)
{
    int bc = blockIdx.z;                 // b*3 + c
    int b  = bc / NCH, c = bc - b*NCH;
    int tI = blockIdx.y, tJ = blockIdx.x;
    int t  = threadIdx.x;

    __shared__ float sxj[64];
    __shared__ float sTab[64*12];        // [j*12 + (0..4)]=cos*yj, [5..9]=sin*yj

    float Bv[NMIX], Pv[NMIX];
    #pragma unroll
    for (int m = 0; m < NMIX; m++) {
        float s = inv_std[m];
        Bv[m] = -0.5f * PI2f * PI2f * LOG2Ef * s * s;
        Pv[m] = PI2f * mu[m];
    }

    if (t < 64) {
        int gj = tJ*64 + t;
        float xjv = xc[(b*ND + gj)*NCH + c];
        float yjv = yc[(b*ND + gj)*NCH + c];
        sxj[t] = xjv;
        #pragma unroll
        for (int m = 0; m < NMIX; m++) {
            float sn, cs;
            __sincosf(Pv[m] * xjv, &sn, &cs);
            sTab[t*12 + m]     = cs * yjv;
            sTab[t*12 + 5 + m] = sn * yjv;
        }
    }
    __syncthreads();

    int i_loc = t >> 2, jq = t & 3;
    int gi = tI*64 + i_loc;
    float xi = xc[(b*ND + gi)*NCH + c];

    float cI[NMIX], sI[NMIX];
    #pragma unroll
    for (int m = 0; m < NMIX; m++)
        __sincosf(Pv[m] * xi, &sI[m], &cI[m]);

    float accC[NMIX], accS[NMIX];
    #pragma unroll
    for (int m = 0; m < NMIX; m++) { accC[m] = 0.f; accS[m] = 0.f; }

    #pragma unroll
    for (int jj = 0; jj < 16; jj++) {
        int j = jq + jj*4;
        float d = xi - sxj[j];
        float e = d * d;
        const float* tp = &sTab[j*12];
        float4 cz  = *reinterpret_cast<const float4*>(tp);       // c0..c3
        float4 mid = *reinterpret_cast<const float4*>(tp + 4);   // c4, s0, s1, s2
        float2 lst = *reinterpret_cast<const float2*>(tp + 8);   // s3, s4
        float v0 = ex2(Bv[0]*e), v1 = ex2(Bv[1]*e), v2 = ex2(Bv[2]*e);
        float v3 = ex2(Bv[3]*e), v4 = ex2(Bv[4]*e);
        accC[0] += v0*cz.x;  accS[0] += v0*mid.y;
        accC[1] += v1*cz.y;  accS[1] += v1*mid.z;
        accC[2] += v2*cz.z;  accS[2] += v2*mid.w;
        accC[3] += v3*cz.w;  accS[3] += v3*lst.x;
        accC[4] += v4*mid.x; accS[4] += v4*lst.y;
    }

    // reduce over the 4 jq lanes (adjacent in warp), then one atomic per (i,m)
    #pragma unroll
    for (int m = 0; m < NMIX; m++) {
        accC[m] += __shfl_xor_sync(0xffffffffu, accC[m], 1);
        accC[m] += __shfl_xor_sync(0xffffffffu, accC[m], 2);
        accS[m] += __shfl_xor_sync(0xffffffffu, accS[m], 1);
        accS[m] += __shfl_xor_sync(0xffffffffu, accS[m], 2);
    }
    if (jq == 0) {
        #pragma unroll
        for (int m = 0; m < NMIX; m++)
            atomicAdd(&g_feat[(bc*NMIX + m)*ND + gi],
                      cI[m]*accC[m] + sI[m]*accS[m]);
    }
}

// ---------------------------------------------------------------------------
// Kernel 34: per-bc hmean (+ re-zero g_feat), then last block runs the MLP
// + Gumbel-softmax. Weights/unif prefetched by every block to hide latency.
// ---------------------------------------------------------------------------
__global__ void __launch_bounds__(256) k34_hmean_mlp(
        const float* __restrict__ yc,
        const float* __restrict__ W1, const float* __restrict__ b1,
        const float* __restrict__ W2, const float* __restrict__ b2,
        const float* __restrict__ W3, const float* __restrict__ b3,
        const float* __restrict__ W4, const float* __restrict__ b4,
        const float* __restrict__ W5, const float* __restrict__ b5,
        const float* __restrict__ unif)
{
    int bc = blockIdx.x;
    int b  = bc / NCH, c = bc - b*NCH;
    int t  = threadIdx.x;

    __shared__ float sW[HH*6], sb[HH], sh[HH];
    __shared__ float w2[300], w3[100], w4[100], w5[150];
    __shared__ float sb2[HH], sb3[HH], sb4[HH], sb5[15];
    __shared__ float su[NB*NS*NCH*NMIX];          // 1200 floats
    __shared__ float shm[NB][30], haL[NB][HH], hbL[NB][HH], ll[NB][15], swacc[NB][15];
    __shared__ bool  isLast;

    for (int u = t; u < 300; u += 256) w2[u] = W2[u];
    for (int u = t; u < 1200; u += 256) su[u] = unif[u];
    if (t < 100) { w3[t] = W3[t]; w4[t] = W4[t]; }
    if (t < 150) w5[t] = W5[t];
    if (t < HH)  { sb2[t] = b2[t]; sb3[t] = b3[t]; sb4[t] = b4[t]; }
    if (t < 15)  sb5[t] = b5[t];
    if (t < HH*6) sW[t] = W1[t];
    if (t < HH)  { sb[t] = b1[t]; sh[t] = 0.f; }
    __syncthreads();

    float hacc[HH];
    #pragma unroll
    for (int k = 0; k < HH; k++) hacc[k] = 0.f;

    for (int i = t; i < ND; i += 256) {
        float ycv = yc[(b*ND + i)*NCH + c];
        float f[6];
        #pragma unroll
        for (int m = 0; m < NMIX; m++) {
            int idx = (bc*NMIX + m)*ND + i;
            f[m] = g_feat[idx] + ZITTERf * ycv;
            g_feat[idx] = 0.f;                    // restore invariant for next replay
        }
        f[5] = ycv;
        #pragma unroll
        for (int k = 0; k < HH; k++) {
            float s = sb[k];
            #pragma unroll
            for (int u = 0; u < 6; u++) s += sW[k*6 + u] * f[u];
            hacc[k] += fmaxf(s, 0.f);
        }
    }
    #pragma unroll
    for (int k = 0; k < HH; k++) atomicAdd(&sh[k], hacc[k]);
    __syncthreads();
    if (t < HH)
        g_hmean[b*(NCH*HH) + c*HH + t] = sh[t] * (1.0f/ND);

    __threadfence();
    __syncthreads();
    if (t == 0) isLast = (atomicAdd(&g_ctr, 1u) == (unsigned)(NB*NCH - 1));
    __syncthreads();
    if (!isLast) return;
    if (t == 0) g_ctr = 0;

    if (t < NB*30) {
        const volatile float* hmv = g_hmean;
        shm[t/30][t%30] = hmv[t];
    }
    if (t < NB*15) swacc[t/15][t%15] = 0.f;
    __syncthreads();

    if (t < NB*HH) {
        int bb = t/HH, k = t%HH;
        float s = sb2[k];
        #pragma unroll
        for (int u = 0; u < 30; u++) s += w2[k*30+u] * shm[bb][u];
        haL[bb][k] = fmaxf(s, 0.f);
    }
    __syncthreads();
    if (t < NB*HH) {
        int bb = t/HH, k = t%HH;
        float s = sb3[k];
        #pragma unroll
        for (int u = 0; u < HH; u++) s += w3[k*HH+u] * haL[bb][u];
        hbL[bb][k] = fmaxf(s, 0.f);
    }
    __syncthreads();
    if (t < NB*HH) {
        int bb = t/HH, k = t%HH;
        float s = sb4[k];
        #pragma unroll
        for (int u = 0; u < HH; u++) s += w4[k*HH+u] * hbL[bb][u];
        haL[bb][k] = fmaxf(s, 0.f);
    }
    __syncthreads();
    if (t < NB*15) {
        int bb = t/15, n = t%15;
        float s = sb5[n];
        #pragma unroll
        for (int k = 0; k < HH; k++) s += w5[n*HH+k] * haL[bb][k];
        ll[bb][n] = s;
    }
    __syncthreads();

    if (t < NB*NS*NCH) {
        int bb = t / (NS*NCH);
        int rem = t % (NS*NCH);
        int s_ = rem / NCH, cc = rem % NCH;
        float z[NMIX], mx = -1e30f;
        #pragma unroll
        for (int m = 0; m < NMIX; m++) {
            float u = su[((bb*NS + s_)*NCH + cc)*NMIX + m];
            float g = -__logf(-__logf(u + 1e-20f));
            z[m] = (g + ll[bb][cc*NMIX + m]) * 10.0f;   // 1/TEMP
            mx = fmaxf(mx, z[m]);
        }
        float sum = 0.f;
        #pragma unroll
        for (int m = 0; m < NMIX; m++) { z[m] = __expf(z[m] - mx); sum += z[m]; }
        float inv = 1.0f / (sum * (float)NS);
        #pragma unroll
        for (int m = 0; m < NMIX; m++)
            atomicAdd(&swacc[bb][cc*NMIX + m], z[m] * inv);
    }
    __syncthreads();
    if (t < NB*NCH*NMIX)
        g_w[t] = swacc[t/(NCH*NMIX)][t%(NCH*NMIX)];
}

// ---------------------------------------------------------------------------
// Kernel B: out[b,i,j,c] = sum_m w[b,c,m]*K_cm(i,j) + diag — trig-separated,
// full grid, no mirror staging. w folded into i-side trig factors.
// Thread: i = t>>2, jq = t&3 covering j = jq*16..jq*16+15 (48 contiguous out
// floats per 4-j chunk -> STG.128 x3). Smem table slot-permuted so the 4
// concurrent j's (stride 16) land on distinct banks.
// ---------------------------------------------------------------------------
__global__ void __launch_bounds__(256) kB_out(float* __restrict__ out,
                                              const float* __restrict__ xc,
                                              const float* __restrict__ mu,
                                              const float* __restrict__ inv_std,
                                              const float* __restrict__ likerr)
{
    int b  = blockIdx.z;
    int tI = blockIdx.y, tJ = blockIdx.x;
    int t  = threadIdx.x;

    __shared__ float tab[64*40];   // slot*40 + c*12 + {0..4 cos,5..9 sin}; +36+c = xj_c

    float Bv[NMIX], Pv[NMIX];
    #pragma unroll
    for (int m = 0; m < NMIX; m++) {
        float s = inv_std[m];
        Bv[m] = -0.5f * PI2f * PI2f * LOG2Ef * s * s;
        Pv[m] = PI2f * mu[m];
    }
    float sd[NCH];
    #pragma unroll
    for (int c = 0; c < NCH; c++) {
        float l = fminf(fmaxf(likerr[c], 0.1f), 1.0f);
        sd[c] = ZITTERf + l*l;
    }

    if (t < 64) {
        int j = t;
        int slot = ((j & 15) << 2) | (j >> 4);
        #pragma unroll
        for (int c = 0; c < NCH; c++) {
            float xjv = xc[(b*ND + tJ*64 + j)*NCH + c];
            tab[slot*40 + 36 + c] = xjv;
            #pragma unroll
            for (int m = 0; m < NMIX; m++) {
                float sn, cs;
                __sincosf(Pv[m] * xjv, &sn, &cs);
                tab[slot*40 + c*12 + m]     = cs;
                tab[slot*40 + c*12 + 5 + m] = sn;
            }
        }
    }
    __syncthreads();

    int i_loc = t >> 2, jq = t & 3;
    int gi = tI*64 + i_loc;

    float xi[NCH], wa[NCH][NMIX], wb[NCH][NMIX];
    #pragma unroll
    for (int c = 0; c < NCH; c++) {
        xi[c] = xc[(b*ND + gi)*NCH + c];
        #pragma unroll
        for (int m = 0; m < NMIX; m++) {
            float sn, cs;
            __sincosf(Pv[m] * xi[c], &sn, &cs);
            float wv = g_w[(b*NCH + c)*NMIX + m];
            wa[c][m] = wv * cs;
            wb[c][m] = wv * sn;
        }
    }

    #pragma unroll
    for (int jc = 0; jc < 4; jc++) {
        float buf[12];
        #pragma unroll
        for (int jj = 0; jj < 4; jj++) {
            int j = jq*16 + jc*4 + jj;
            int slot = ((j & 15) << 2) | (j >> 4);
            int gj = tJ*64 + j;
            const float* sp = &tab[slot*40];
            #pragma unroll
            for (int c = 0; c < NCH; c++) {
                const float* tp = sp + c*12;
                float4 cz  = *reinterpret_cast<const float4*>(tp);
                float4 mid = *reinterpret_cast<const float4*>(tp + 4);
                float2 lst = *reinterpret_cast<const float2*>(tp + 8);
                float d = xi[c] - sp[36 + c];
                float e = d * d;
                float acc;
                float T0 = wa[c][0]*cz.x  + wb[c][0]*mid.y;
                float T1 = wa[c][1]*cz.y  + wb[c][1]*mid.z;
                float T2 = wa[c][2]*cz.z  + wb[c][2]*mid.w;
                float T3 = wa[c][3]*cz.w  + wb[c][3]*lst.x;
                float T4 = wa[c][4]*mid.x + wb[c][4]*lst.y;
                acc  = ex2(Bv[0]*e) * T0;
                acc += ex2(Bv[1]*e) * T1;
                acc += ex2(Bv[2]*e) * T2;
                acc += ex2(Bv[3]*e) * T3;
                acc += ex2(Bv[4]*e) * T4;
                if (gi == gj) acc += sd[c];
                buf[jj*NCH + c] = acc;
            }
        }
        size_t base = ((size_t)(b*ND + gi)*ND + tJ*64 + jq*16 + jc*4) * NCH;
        float4* p = reinterpret_cast<float4*>(out + base);
        p[0] = make_float4(buf[0], buf[1], buf[2],  buf[3]);
        p[1] = make_float4(buf[4], buf[5], buf[6],  buf[7]);
        p[2] = make_float4(buf[8], buf[9], buf[10], buf[11]);
    }
}

// ---------------------------------------------------------------------------
extern "C" void kernel_launch(void* const* d_in, const int* in_sizes, int n_in,
                              void* d_out, int out_size)
{
    const float* xc      = (const float*)d_in[0];
    const float* yc      = (const float*)d_in[1];
    const float* mu      = (const float*)d_in[2];
    const float* inv_std = (const float*)d_in[3];
    const float* likerr  = (const float*)d_in[4];
    const float* unif    = (const float*)d_in[5];
    const float* W1 = (const float*)d_in[6];  const float* b1 = (const float*)d_in[7];
    const float* W2 = (const float*)d_in[8];  const float* b2 = (const float*)d_in[9];
    const float* W3 = (const float*)d_in[10]; const float* b3 = (const float*)d_in[11];
    const float* W4 = (const float*)d_in[12]; const float* b4 = (const float*)d_in[13];
    const float* W5 = (const float*)d_in[14]; const float* b5 = (const float*)d_in[15];
    float* out = (float*)d_out;

    kA_feat <<< dim3(ND/64, ND/64, NB*NCH), 256 >>>(xc, yc, mu, inv_std);
    k34_hmean_mlp <<< NB*NCH, 256 >>>(yc, W1, b1, W2, b2, W3, b3, W4, b4, W5, b5, unif);
    kB_out  <<< dim3(ND/64, ND/64, NB), 256 >>>(out, xc, mu, inv_std, likerr);
}

// round 6
// speedup vs baseline: 1.6560x; 1.6560x over previous
#include <cuda_runtime.h>
#include <math.h>

#define ND   768
#define NB   8
#define NCH  3
#define NMIX 5
#define NS   10
#define HH   10
#define PI2f 6.28318530717958647692f
#define ZITTERf 1e-4f
#define NPLANE (NB*NCH*NMIX)          // 120
#define LOG2Ef 1.4426950408889634f

// padded j-index: conflict-free for the 4 concurrent jq groups, float4-aligned
#define JPAD 88
#define PADJ(j) ((j) + (((j) >> 4) << 3))

__device__ float    g_feat[NPLANE * ND];   // zero-init; kA atomics; k34 reads then re-zeroes
__device__ float    g_hmean[NB * NCH * HH];
__device__ float    g_w[NB * NCH * NMIX];
__device__ unsigned g_ctr;                 // zero-init; k34 last-block counter (self-resetting)

__device__ __forceinline__ float ex2(float x) {
    float y; asm("ex2.approx.ftz.f32 %0, %1;" : "=f"(y) : "f"(x)); return y;
}

// ---------------------------------------------------------------------------
// Kernel A: feature[bc,m,i] = sum_j K_m(i,j)*yc[j], trig-separated:
//   K = exp2(B*d^2) * (cI*cJ + sI*sJ);  cJ*yj, sJ*yj in smem tables [m][j],
//   read as float4 (1 LDS.128 per 4 evals). Full grid.
// Thread: i = t>>2 (one row), jq = t&3 (16 consecutive j's).
// ---------------------------------------------------------------------------
__global__ void __launch_bounds__(256) kA_feat(const float* __restrict__ xc,
                                               const float* __restrict__ yc,
                                               const float* __restrict__ mu,
                                               const float* __restrict__ inv_std)
{
    int bc = blockIdx.z;                 // b*3 + c
    int b  = bc / NCH, c = bc - b*NCH;
    int tI = blockIdx.y, tJ = blockIdx.x;
    int t  = threadIdx.x;

    __shared__ float sC[NMIX*JPAD], sS[NMIX*JPAD], sXj[JPAD];

    float Bv[NMIX], Pv[NMIX];
    #pragma unroll
    for (int m = 0; m < NMIX; m++) {
        float s = inv_std[m];
        Bv[m] = -0.5f * PI2f * PI2f * LOG2Ef * s * s;
        Pv[m] = PI2f * mu[m];
    }

    if (t < 64) {
        int gj = tJ*64 + t;
        float xjv = xc[(b*ND + gj)*NCH + c];
        float yjv = yc[(b*ND + gj)*NCH + c];
        int pj = PADJ(t);
        sXj[pj] = xjv;
        #pragma unroll
        for (int m = 0; m < NMIX; m++) {
            float sn, cs;
            __sincosf(Pv[m] * xjv, &sn, &cs);
            sC[m*JPAD + pj] = cs * yjv;
            sS[m*JPAD + pj] = sn * yjv;
        }
    }
    __syncthreads();

    int i_loc = t >> 2, jq = t & 3;
    int gi = tI*64 + i_loc;
    float xi = xc[(b*ND + gi)*NCH + c];

    float cI[NMIX], sI[NMIX];
    #pragma unroll
    for (int m = 0; m < NMIX; m++)
        __sincosf(Pv[m] * xi, &sI[m], &cI[m]);

    // e[16] precomputed in registers
    float e[16];
    #pragma unroll
    for (int q = 0; q < 4; q++) {
        float4 xv = *reinterpret_cast<const float4*>(&sXj[jq*24 + q*4]);
        float d0 = xi - xv.x, d1 = xi - xv.y, d2 = xi - xv.z, d3 = xi - xv.w;
        e[q*4+0] = d0*d0; e[q*4+1] = d1*d1; e[q*4+2] = d2*d2; e[q*4+3] = d3*d3;
    }

    float accC[NMIX], accS[NMIX];
    #pragma unroll
    for (int m = 0; m < NMIX; m++) { accC[m] = 0.f; accS[m] = 0.f; }

    #pragma unroll
    for (int m = 0; m < NMIX; m++) {
        float Bm = Bv[m];
        float aC = 0.f, aS = 0.f;
        #pragma unroll
        for (int q = 0; q < 4; q++) {
            int slot = jq*24 + q*4;
            float4 cj = *reinterpret_cast<const float4*>(&sC[m*JPAD + slot]);
            float4 sj = *reinterpret_cast<const float4*>(&sS[m*JPAD + slot]);
            float v0 = ex2(Bm*e[q*4+0]);
            float v1 = ex2(Bm*e[q*4+1]);
            float v2 = ex2(Bm*e[q*4+2]);
            float v3 = ex2(Bm*e[q*4+3]);
            aC += v0*cj.x + v1*cj.y + v2*cj.z + v3*cj.w;
            aS += v0*sj.x + v1*sj.y + v2*sj.z + v3*sj.w;
        }
        accC[m] = aC; accS[m] = aS;
    }

    // reduce over the 4 jq lanes, then one atomic per (i,m)
    #pragma unroll
    for (int m = 0; m < NMIX; m++) {
        accC[m] += __shfl_xor_sync(0xffffffffu, accC[m], 1);
        accC[m] += __shfl_xor_sync(0xffffffffu, accC[m], 2);
        accS[m] += __shfl_xor_sync(0xffffffffu, accS[m], 1);
        accS[m] += __shfl_xor_sync(0xffffffffu, accS[m], 2);
    }
    if (jq == 0) {
        #pragma unroll
        for (int m = 0; m < NMIX; m++)
            atomicAdd(&g_feat[(bc*NMIX + m)*ND + gi],
                      cI[m]*accC[m] + sI[m]*accS[m]);
    }
}

// ---------------------------------------------------------------------------
// Kernel 34: per-bc hmean (+ re-zero g_feat), then last block runs the MLP
// + Gumbel-softmax. Weights/unif prefetched by every block to hide latency.
// ---------------------------------------------------------------------------
__global__ void __launch_bounds__(256) k34_hmean_mlp(
        const float* __restrict__ yc,
        const float* __restrict__ W1, const float* __restrict__ b1,
        const float* __restrict__ W2, const float* __restrict__ b2,
        const float* __restrict__ W3, const float* __restrict__ b3,
        const float* __restrict__ W4, const float* __restrict__ b4,
        const float* __restrict__ W5, const float* __restrict__ b5,
        const float* __restrict__ unif)
{
    int bc = blockIdx.x;
    int b  = bc / NCH, c = bc - b*NCH;
    int t  = threadIdx.x;

    __shared__ float sW[HH*6], sb[HH], sh[HH];
    __shared__ float w2[300], w3[100], w4[100], w5[150];
    __shared__ float sb2[HH], sb3[HH], sb4[HH], sb5[15];
    __shared__ float su[NB*NS*NCH*NMIX];          // 1200 floats
    __shared__ float shm[NB][30], haL[NB][HH], hbL[NB][HH], ll[NB][15], swacc[NB][15];
    __shared__ bool  isLast;

    for (int u = t; u < 300; u += 256) w2[u] = W2[u];
    for (int u = t; u < 1200; u += 256) su[u] = unif[u];
    if (t < 100) { w3[t] = W3[t]; w4[t] = W4[t]; }
    if (t < 150) w5[t] = W5[t];
    if (t < HH)  { sb2[t] = b2[t]; sb3[t] = b3[t]; sb4[t] = b4[t]; }
    if (t < 15)  sb5[t] = b5[t];
    if (t < HH*6) sW[t] = W1[t];
    if (t < HH)  { sb[t] = b1[t]; sh[t] = 0.f; }
    __syncthreads();

    float hacc[HH];
    #pragma unroll
    for (int k = 0; k < HH; k++) hacc[k] = 0.f;

    for (int i = t; i < ND; i += 256) {
        float ycv = yc[(b*ND + i)*NCH + c];
        float f[6];
        #pragma unroll
        for (int m = 0; m < NMIX; m++) {
            int idx = (bc*NMIX + m)*ND + i;
            f[m] = g_feat[idx] + ZITTERf * ycv;
            g_feat[idx] = 0.f;                    // restore invariant for next replay
        }
        f[5] = ycv;
        #pragma unroll
        for (int k = 0; k < HH; k++) {
            float s = sb[k];
            #pragma unroll
            for (int u = 0; u < 6; u++) s += sW[k*6 + u] * f[u];
            hacc[k] += fmaxf(s, 0.f);
        }
    }
    #pragma unroll
    for (int k = 0; k < HH; k++) atomicAdd(&sh[k], hacc[k]);
    __syncthreads();
    if (t < HH)
        g_hmean[b*(NCH*HH) + c*HH + t] = sh[t] * (1.0f/ND);

    __threadfence();
    __syncthreads();
    if (t == 0) isLast = (atomicAdd(&g_ctr, 1u) == (unsigned)(NB*NCH - 1));
    __syncthreads();
    if (!isLast) return;
    if (t == 0) g_ctr = 0;

    if (t < NB*30) {
        const volatile float* hmv = g_hmean;
        shm[t/30][t%30] = hmv[t];
    }
    if (t < NB*15) swacc[t/15][t%15] = 0.f;
    __syncthreads();

    if (t < NB*HH) {
        int bb = t/HH, k = t%HH;
        float s = sb2[k];
        #pragma unroll
        for (int u = 0; u < 30; u++) s += w2[k*30+u] * shm[bb][u];
        haL[bb][k] = fmaxf(s, 0.f);
    }
    __syncthreads();
    if (t < NB*HH) {
        int bb = t/HH, k = t%HH;
        float s = sb3[k];
        #pragma unroll
        for (int u = 0; u < HH; u++) s += w3[k*HH+u] * haL[bb][u];
        hbL[bb][k] = fmaxf(s, 0.f);
    }
    __syncthreads();
    if (t < NB*HH) {
        int bb = t/HH, k = t%HH;
        float s = sb4[k];
        #pragma unroll
        for (int u = 0; u < HH; u++) s += w4[k*HH+u] * hbL[bb][u];
        haL[bb][k] = fmaxf(s, 0.f);
    }
    __syncthreads();
    if (t < NB*15) {
        int bb = t/15, n = t%15;
        float s = sb5[n];
        #pragma unroll
        for (int k = 0; k < HH; k++) s += w5[n*HH+k] * haL[bb][k];
        ll[bb][n] = s;
    }
    __syncthreads();

    if (t < NB*NS*NCH) {
        int bb = t / (NS*NCH);
        int rem = t % (NS*NCH);
        int s_ = rem / NCH, cc = rem % NCH;
        float z[NMIX], mx = -1e30f;
        #pragma unroll
        for (int m = 0; m < NMIX; m++) {
            float u = su[((bb*NS + s_)*NCH + cc)*NMIX + m];
            float g = -__logf(-__logf(u + 1e-20f));
            z[m] = (g + ll[bb][cc*NMIX + m]) * 10.0f;   // 1/TEMP
            mx = fmaxf(mx, z[m]);
        }
        float sum = 0.f;
        #pragma unroll
        for (int m = 0; m < NMIX; m++) { z[m] = __expf(z[m] - mx); sum += z[m]; }
        float inv = 1.0f / (sum * (float)NS);
        #pragma unroll
        for (int m = 0; m < NMIX; m++)
            atomicAdd(&swacc[bb][cc*NMIX + m], z[m] * inv);
    }
    __syncthreads();
    if (t < NB*NCH*NMIX)
        g_w[t] = swacc[t/(NCH*NMIX)][t%(NCH*NMIX)];
}

// ---------------------------------------------------------------------------
// Kernel B: out[b,i,j,c] = sum_m w[b,c,m]*K_cm(i,j) + diag — trig-separated,
// w folded into the j-side smem tables (block is per-b). Tables [c][m][j],
// float4 reads. Full grid, q-chunked accumulators (12 regs live), stores
// 3x STG.128 per chunk.
// Thread: i = t>>2, jq = t&3 covering j = jq*16..jq*16+15.
// ---------------------------------------------------------------------------
__global__ void __launch_bounds__(256) kB_out(float* __restrict__ out,
                                              const float* __restrict__ xc,
                                              const float* __restrict__ mu,
                                              const float* __restrict__ inv_std,
                                              const float* __restrict__ likerr)
{
    int b  = blockIdx.z;
    int tI = blockIdx.y, tJ = blockIdx.x;
    int t  = threadIdx.x;

    __shared__ float sC[NCH*NMIX*JPAD], sS[NCH*NMIX*JPAD], sXj[NCH*JPAD];

    float Bv[NMIX], Pv[NMIX];
    #pragma unroll
    for (int m = 0; m < NMIX; m++) {
        float s = inv_std[m];
        Bv[m] = -0.5f * PI2f * PI2f * LOG2Ef * s * s;
        Pv[m] = PI2f * mu[m];
    }
    float sd[NCH];
    #pragma unroll
    for (int c = 0; c < NCH; c++) {
        float l = fminf(fmaxf(likerr[c], 0.1f), 1.0f);
        sd[c] = ZITTERf + l*l;
    }

    if (t < 64) {
        int pj = PADJ(t);
        #pragma unroll
        for (int c = 0; c < NCH; c++) {
            float xjv = xc[(b*ND + tJ*64 + t)*NCH + c];
            sXj[c*JPAD + pj] = xjv;
            #pragma unroll
            for (int m = 0; m < NMIX; m++) {
                float sn, cs;
                __sincosf(Pv[m] * xjv, &sn, &cs);
                float wv = g_w[(b*NCH + c)*NMIX + m];
                sC[(c*NMIX + m)*JPAD + pj] = cs * wv;
                sS[(c*NMIX + m)*JPAD + pj] = sn * wv;
            }
        }
    }
    __syncthreads();

    int i_loc = t >> 2, jq = t & 3;
    int gi = tI*64 + i_loc;

    float xi[NCH], cI[NCH][NMIX], sI[NCH][NMIX];
    #pragma unroll
    for (int c = 0; c < NCH; c++) {
        xi[c] = xc[(b*ND + gi)*NCH + c];
        #pragma unroll
        for (int m = 0; m < NMIX; m++)
            __sincosf(Pv[m] * xi[c], &sI[c][m], &cI[c][m]);
    }

    bool diagT = (tI == tJ) && ((i_loc >> 4) == jq);
    int  dq = (i_loc & 15) >> 2, dk = i_loc & 3;

    #pragma unroll
    for (int q = 0; q < 4; q++) {
        int slot = jq*24 + q*4;
        float a12[12];
        #pragma unroll
        for (int u = 0; u < 12; u++) a12[u] = 0.f;

        #pragma unroll
        for (int c = 0; c < NCH; c++) {
            float4 xv = *reinterpret_cast<const float4*>(&sXj[c*JPAD + slot]);
            float d0 = xi[c] - xv.x, d1 = xi[c] - xv.y,
                  d2 = xi[c] - xv.z, d3 = xi[c] - xv.w;
            float e0 = d0*d0, e1 = d1*d1, e2 = d2*d2, e3 = d3*d3;
            float acc0 = 0.f, acc1 = 0.f, acc2 = 0.f, acc3 = 0.f;
            #pragma unroll
            for (int m = 0; m < NMIX; m++) {
                float Bm = Bv[m], cIm = cI[c][m], sIm = sI[c][m];
                float4 cj = *reinterpret_cast<const float4*>(&sC[(c*NMIX + m)*JPAD + slot]);
                float4 sj = *reinterpret_cast<const float4*>(&sS[(c*NMIX + m)*JPAD + slot]);
                acc0 += ex2(Bm*e0) * (cIm*cj.x + sIm*sj.x);
                acc1 += ex2(Bm*e1) * (cIm*cj.y + sIm*sj.y);
                acc2 += ex2(Bm*e2) * (cIm*cj.z + sIm*sj.z);
                acc3 += ex2(Bm*e3) * (cIm*cj.w + sIm*sj.w);
            }
            a12[0*NCH + c] = acc0; a12[1*NCH + c] = acc1;
            a12[2*NCH + c] = acc2; a12[3*NCH + c] = acc3;
        }

        if (diagT && dq == q) {
            #pragma unroll
            for (int c = 0; c < NCH; c++) a12[dk*NCH + c] += sd[c];
        }

        size_t base = ((size_t)(b*ND + gi)*ND + tJ*64 + jq*16 + q*4) * NCH;
        float4* p = reinterpret_cast<float4*>(out + base);
        p[0] = make_float4(a12[0], a12[1], a12[2],  a12[3]);
        p[1] = make_float4(a12[4], a12[5], a12[6],  a12[7]);
        p[2] = make_float4(a12[8], a12[9], a12[10], a12[11]);
    }
}

// ---------------------------------------------------------------------------
extern "C" void kernel_launch(void* const* d_in, const int* in_sizes, int n_in,
                              void* d_out, int out_size)
{
    const float* xc      = (const float*)d_in[0];
    const float* yc      = (const float*)d_in[1];
    const float* mu      = (const float*)d_in[2];
    const float* inv_std = (const float*)d_in[3];
    const float* likerr  = (const float*)d_in[4];
    const float* unif    = (const float*)d_in[5];
    const float* W1 = (const float*)d_in[6];  const float* b1 = (const float*)d_in[7];
    const float* W2 = (const float*)d_in[8];  const float* b2 = (const float*)d_in[9];
    const float* W3 = (const float*)d_in[10]; const float* b3 = (const float*)d_in[11];
    const float* W4 = (const float*)d_in[12]; const float* b4 = (const float*)d_in[13];
    const float* W5 = (const float*)d_in[14]; const float* b5 = (const float*)d_in[15];
    float* out = (float*)d_out;

    kA_feat <<< dim3(ND/64, ND/64, NB*NCH), 256 >>>(xc, yc, mu, inv_std);
    k34_hmean_mlp <<< NB*NCH, 256 >>>(yc, W1, b1, W2, b2, W3, b3, W4, b4, W5, b5, unif);
    kB_out  <<< dim3(ND/64, ND/64, NB), 256 >>>(out, xc, mu, inv_std, likerr);
}

// round 7
// speedup vs baseline: 1.7882x; 1.0799x over previous
#include <cuda_runtime.h>
#include <math.h>

#define ND   768
#define NB   8
#define NCH  3
#define NMIX 5
#define NS   10
#define HH   10
#define PI2f 6.28318530717958647692f
#define ZITTERf 1e-4f
#define NPLANE (NB*NCH*NMIX)          // 120
#define LOG2Ef 1.4426950408889634f

__device__ float    g_feat[NPLANE * ND];   // zero-init; kA atomics; k34 reads then re-zeroes
__device__ float    g_hmean[NB * NCH * HH];
__device__ float    g_w[NB * NCH * NMIX];
__device__ unsigned g_ctr;                 // zero-init; k34 last-block counter (self-resetting)

__device__ __forceinline__ float ex2(float x) {
    float y; asm("ex2.approx.ftz.f32 %0, %1;" : "=f"(y) : "f"(x)); return y;
}

// ---------------------------------------------------------------------------
// Kernel A: feature[bc,m,i] = sum_j K_m(i,j)*yc[j], trig-separated.
// Tile: 64 i x 256 j (setup amortized 4x vs 64j). Thread: i = t>>2, jq = t&3
// covering 64 consecutive j (group base jq*72 in padded table).
// Padding: pj = j + (j>>6)*8 -> group stride 72 floats == 8 mod 32: the 4
// concurrent jq float4 reads hit disjoint banks, 8-way i-broadcast.
// ---------------------------------------------------------------------------
#define JPA 280    // padded table stride for 256 j

__global__ void __launch_bounds__(256) kA_feat(const float* __restrict__ xc,
                                               const float* __restrict__ yc,
                                               const float* __restrict__ mu,
                                               const float* __restrict__ inv_std)
{
    int bc  = blockIdx.z;                 // b*3 + c
    int b   = bc / NCH, c = bc - b*NCH;
    int it  = blockIdx.y;
    int jt0 = blockIdx.x * 256;
    int t   = threadIdx.x;

    __shared__ float sC[NMIX*JPA], sS[NMIX*JPA], sXj[JPA];

    float Bv[NMIX], Pv[NMIX];
    #pragma unroll
    for (int m = 0; m < NMIX; m++) {
        float s = inv_std[m];
        Bv[m] = -0.5f * PI2f * PI2f * LOG2Ef * s * s;
        Pv[m] = PI2f * mu[m];
    }

    {   // table setup: every thread owns one j
        int j  = t;
        int gj = jt0 + j;
        float xjv = xc[(b*ND + gj)*NCH + c];
        float yjv = yc[(b*ND + gj)*NCH + c];
        int pj = j + ((j >> 6) << 3);
        sXj[pj] = xjv;
        #pragma unroll
        for (int m = 0; m < NMIX; m++) {
            float sn, cs;
            __sincosf(Pv[m] * xjv, &sn, &cs);
            sC[m*JPA + pj] = cs * yjv;
            sS[m*JPA + pj] = sn * yjv;
        }
    }
    __syncthreads();

    int i_loc = t >> 2, jq = t & 3;
    int gi = it*64 + i_loc;
    float xi = xc[(b*ND + gi)*NCH + c];

    float cI[NMIX], sI[NMIX];
    #pragma unroll
    for (int m = 0; m < NMIX; m++)
        __sincosf(Pv[m] * xi, &sI[m], &cI[m]);

    float accC[NMIX], accS[NMIX];
    #pragma unroll
    for (int m = 0; m < NMIX; m++) { accC[m] = 0.f; accS[m] = 0.f; }

    int gbase = jq * 72;
    #pragma unroll 4
    for (int ch = 0; ch < 16; ch++) {
        int off = gbase + ch*4;
        float4 xv = *reinterpret_cast<const float4*>(&sXj[off]);
        float d0 = xi - xv.x, d1 = xi - xv.y, d2 = xi - xv.z, d3 = xi - xv.w;
        float e0 = d0*d0, e1 = d1*d1, e2 = d2*d2, e3 = d3*d3;
        #pragma unroll
        for (int m = 0; m < NMIX; m++) {
            float Bm = Bv[m];
            float4 cj = *reinterpret_cast<const float4*>(&sC[m*JPA + off]);
            float4 sj = *reinterpret_cast<const float4*>(&sS[m*JPA + off]);
            float v0 = ex2(Bm*e0), v1 = ex2(Bm*e1), v2 = ex2(Bm*e2), v3 = ex2(Bm*e3);
            accC[m] += v0*cj.x + v1*cj.y + v2*cj.z + v3*cj.w;
            accS[m] += v0*sj.x + v1*sj.y + v2*sj.z + v3*sj.w;
        }
    }

    #pragma unroll
    for (int m = 0; m < NMIX; m++) {
        accC[m] += __shfl_xor_sync(0xffffffffu, accC[m], 1);
        accC[m] += __shfl_xor_sync(0xffffffffu, accC[m], 2);
        accS[m] += __shfl_xor_sync(0xffffffffu, accS[m], 1);
        accS[m] += __shfl_xor_sync(0xffffffffu, accS[m], 2);
    }
    if (jq == 0) {
        #pragma unroll
        for (int m = 0; m < NMIX; m++)
            atomicAdd(&g_feat[(bc*NMIX + m)*ND + gi],
                      cI[m]*accC[m] + sI[m]*accS[m]);
    }
}

// ---------------------------------------------------------------------------
// Kernel 34: per-bc hmean (+ re-zero g_feat), then last block runs the MLP
// + Gumbel-softmax. Weights/unif prefetched by every block to hide latency.
// ---------------------------------------------------------------------------
__global__ void __launch_bounds__(256) k34_hmean_mlp(
        const float* __restrict__ yc,
        const float* __restrict__ W1, const float* __restrict__ b1,
        const float* __restrict__ W2, const float* __restrict__ b2,
        const float* __restrict__ W3, const float* __restrict__ b3,
        const float* __restrict__ W4, const float* __restrict__ b4,
        const float* __restrict__ W5, const float* __restrict__ b5,
        const float* __restrict__ unif)
{
    int bc = blockIdx.x;
    int b  = bc / NCH, c = bc - b*NCH;
    int t  = threadIdx.x;

    __shared__ float sW[HH*6], sb[HH], sh[HH];
    __shared__ float w2[300], w3[100], w4[100], w5[150];
    __shared__ float sb2[HH], sb3[HH], sb4[HH], sb5[15];
    __shared__ float su[NB*NS*NCH*NMIX];          // 1200 floats
    __shared__ float shm[NB][30], haL[NB][HH], hbL[NB][HH], ll[NB][15], swacc[NB][15];
    __shared__ bool  isLast;

    for (int u = t; u < 300; u += 256) w2[u] = W2[u];
    for (int u = t; u < 1200; u += 256) su[u] = unif[u];
    if (t < 100) { w3[t] = W3[t]; w4[t] = W4[t]; }
    if (t < 150) w5[t] = W5[t];
    if (t < HH)  { sb2[t] = b2[t]; sb3[t] = b3[t]; sb4[t] = b4[t]; }
    if (t < 15)  sb5[t] = b5[t];
    if (t < HH*6) sW[t] = W1[t];
    if (t < HH)  { sb[t] = b1[t]; sh[t] = 0.f; }
    __syncthreads();

    float hacc[HH];
    #pragma unroll
    for (int k = 0; k < HH; k++) hacc[k] = 0.f;

    for (int i = t; i < ND; i += 256) {
        float ycv = yc[(b*ND + i)*NCH + c];
        float f[6];
        #pragma unroll
        for (int m = 0; m < NMIX; m++) {
            int idx = (bc*NMIX + m)*ND + i;
            f[m] = g_feat[idx] + ZITTERf * ycv;
            g_feat[idx] = 0.f;                    // restore invariant for next replay
        }
        f[5] = ycv;
        #pragma unroll
        for (int k = 0; k < HH; k++) {
            float s = sb[k];
            #pragma unroll
            for (int u = 0; u < 6; u++) s += sW[k*6 + u] * f[u];
            hacc[k] += fmaxf(s, 0.f);
        }
    }
    #pragma unroll
    for (int k = 0; k < HH; k++) atomicAdd(&sh[k], hacc[k]);
    __syncthreads();
    if (t < HH)
        g_hmean[b*(NCH*HH) + c*HH + t] = sh[t] * (1.0f/ND);

    __threadfence();
    __syncthreads();
    if (t == 0) isLast = (atomicAdd(&g_ctr, 1u) == (unsigned)(NB*NCH - 1));
    __syncthreads();
    if (!isLast) return;
    if (t == 0) g_ctr = 0;

    if (t < NB*30) {
        const volatile float* hmv = g_hmean;
        shm[t/30][t%30] = hmv[t];
    }
    if (t < NB*15) swacc[t/15][t%15] = 0.f;
    __syncthreads();

    if (t < NB*HH) {
        int bb = t/HH, k = t%HH;
        float s = sb2[k];
        #pragma unroll
        for (int u = 0; u < 30; u++) s += w2[k*30+u] * shm[bb][u];
        haL[bb][k] = fmaxf(s, 0.f);
    }
    __syncthreads();
    if (t < NB*HH) {
        int bb = t/HH, k = t%HH;
        float s = sb3[k];
        #pragma unroll
        for (int u = 0; u < HH; u++) s += w3[k*HH+u] * haL[bb][u];
        hbL[bb][k] = fmaxf(s, 0.f);
    }
    __syncthreads();
    if (t < NB*HH) {
        int bb = t/HH, k = t%HH;
        float s = sb4[k];
        #pragma unroll
        for (int u = 0; u < HH; u++) s += w4[k*HH+u] * hbL[bb][u];
        haL[bb][k] = fmaxf(s, 0.f);
    }
    __syncthreads();
    if (t < NB*15) {
        int bb = t/15, n = t%15;
        float s = sb5[n];
        #pragma unroll
        for (int k = 0; k < HH; k++) s += w5[n*HH+k] * haL[bb][k];
        ll[bb][n] = s;
    }
    __syncthreads();

    if (t < NB*NS*NCH) {
        int bb = t / (NS*NCH);
        int rem = t % (NS*NCH);
        int s_ = rem / NCH, cc = rem % NCH;
        float z[NMIX], mx = -1e30f;
        #pragma unroll
        for (int m = 0; m < NMIX; m++) {
            float u = su[((bb*NS + s_)*NCH + cc)*NMIX + m];
            float g = -__logf(-__logf(u + 1e-20f));
            z[m] = (g + ll[bb][cc*NMIX + m]) * 10.0f;   // 1/TEMP
            mx = fmaxf(mx, z[m]);
        }
        float sum = 0.f;
        #pragma unroll
        for (int m = 0; m < NMIX; m++) { z[m] = __expf(z[m] - mx); sum += z[m]; }
        float inv = 1.0f / (sum * (float)NS);
        #pragma unroll
        for (int m = 0; m < NMIX; m++)
            atomicAdd(&swacc[bb][cc*NMIX + m], z[m] * inv);
    }
    __syncthreads();
    if (t < NB*NCH*NMIX)
        g_w[t] = swacc[t/(NCH*NMIX)][t%(NCH*NMIX)];
}

// ---------------------------------------------------------------------------
// Kernel B: out[b,i,j,c] = sum_m w[b,c,m]*K_cm(i,j) + diag — trig-separated,
// SYMMETRIC: only tiles tJ>=tI; off-diag tiles stage the mirror in smem
// (stride 196, float4-clean) and write it coalesced. w folded into j tables.
// Dynamic smem (~62 KB). Thread: i = t>>2, jq = t&3 over j = jq*16..+15.
// ---------------------------------------------------------------------------
#define KB_JPAD 88
#define KB_MSTR 196
#define KB_SM_F   (64*KB_MSTR)                 // 12544 mirror floats
#define KB_C_OFF  KB_SM_F                      // 15*88 = 1320
#define KB_S_OFF  (KB_C_OFF + NCH*NMIX*KB_JPAD)
#define KB_XJ_OFF (KB_S_OFF + NCH*NMIX*KB_JPAD)
#define KB_TOT_F  (KB_XJ_OFF + NCH*KB_JPAD)    // total floats
#define KB_TOT_B  (KB_TOT_F * 4)

__global__ void __launch_bounds__(256) kB_out(float* __restrict__ out,
                                              const float* __restrict__ xc,
                                              const float* __restrict__ mu,
                                              const float* __restrict__ inv_std,
                                              const float* __restrict__ likerr)
{
    int b  = blockIdx.z;
    int tI = blockIdx.y, tJ = blockIdx.x;
    if (tJ < tI) return;
    bool offdiag = (tI != tJ);

    extern __shared__ float smem[];
    float* sM  = smem;                 // mirror staging [j][i*3+c], stride 196
    float* sC  = smem + KB_C_OFF;      // [c*5+m][pj]  (cos * w)
    float* sS  = smem + KB_S_OFF;      // [c*5+m][pj]  (sin * w)
    float* sXj = smem + KB_XJ_OFF;     // [c][pj]

    int t = threadIdx.x;

    float Bv[NMIX], Pv[NMIX];
    #pragma unroll
    for (int m = 0; m < NMIX; m++) {
        float s = inv_std[m];
        Bv[m] = -0.5f * PI2f * PI2f * LOG2Ef * s * s;
        Pv[m] = PI2f * mu[m];
    }
    float sd[NCH];
    #pragma unroll
    for (int c = 0; c < NCH; c++) {
        float l = fminf(fmaxf(likerr[c], 0.1f), 1.0f);
        sd[c] = ZITTERf + l*l;
    }

    if (t < 64) {
        int pj = t + ((t >> 4) << 3);
        #pragma unroll
        for (int c = 0; c < NCH; c++) {
            float xjv = xc[(b*ND + tJ*64 + t)*NCH + c];
            sXj[c*KB_JPAD + pj] = xjv;
            #pragma unroll
            for (int m = 0; m < NMIX; m++) {
                float sn, cs;
                __sincosf(Pv[m] * xjv, &sn, &cs);
                float wv = g_w[(b*NCH + c)*NMIX + m];
                sC[(c*NMIX + m)*KB_JPAD + pj] = cs * wv;
                sS[(c*NMIX + m)*KB_JPAD + pj] = sn * wv;
            }
        }
    }
    __syncthreads();

    int i_loc = t >> 2, jq = t & 3;
    int gi = tI*64 + i_loc;

    float xi[NCH], cI[NCH][NMIX], sI[NCH][NMIX];
    #pragma unroll
    for (int c = 0; c < NCH; c++) {
        xi[c] = xc[(b*ND + gi)*NCH + c];
        #pragma unroll
        for (int m = 0; m < NMIX; m++)
            __sincosf(Pv[m] * xi[c], &sI[c][m], &cI[c][m]);
    }

    bool diagT = (!offdiag) && ((i_loc >> 4) == jq);
    int  dq = (i_loc & 15) >> 2, dk = i_loc & 3;

    #pragma unroll
    for (int q = 0; q < 4; q++) {
        int slot = jq*24 + q*4;
        float a12[12];
        #pragma unroll
        for (int c = 0; c < NCH; c++) {
            float4 xv = *reinterpret_cast<const float4*>(&sXj[c*KB_JPAD + slot]);
            float d0 = xi[c] - xv.x, d1 = xi[c] - xv.y,
                  d2 = xi[c] - xv.z, d3 = xi[c] - xv.w;
            float e0 = d0*d0, e1 = d1*d1, e2 = d2*d2, e3 = d3*d3;
            float acc0 = 0.f, acc1 = 0.f, acc2 = 0.f, acc3 = 0.f;
            #pragma unroll
            for (int m = 0; m < NMIX; m++) {
                float Bm = Bv[m], cIm = cI[c][m], sIm = sI[c][m];
                float4 cj = *reinterpret_cast<const float4*>(&sC[(c*NMIX + m)*KB_JPAD + slot]);
                float4 sj = *reinterpret_cast<const float4*>(&sS[(c*NMIX + m)*KB_JPAD + slot]);
                acc0 += ex2(Bm*e0) * (cIm*cj.x + sIm*sj.x);
                acc1 += ex2(Bm*e1) * (cIm*cj.y + sIm*sj.y);
                acc2 += ex2(Bm*e2) * (cIm*cj.z + sIm*sj.z);
                acc3 += ex2(Bm*e3) * (cIm*cj.w + sIm*sj.w);
            }
            a12[0*NCH + c] = acc0; a12[1*NCH + c] = acc1;
            a12[2*NCH + c] = acc2; a12[3*NCH + c] = acc3;
        }

        if (diagT && dq == q) {
            #pragma unroll
            for (int c = 0; c < NCH; c++) a12[dk*NCH + c] += sd[c];
        }

        size_t base = ((size_t)(b*ND + gi)*ND + tJ*64 + jq*16 + q*4) * NCH;
        float4* p = reinterpret_cast<float4*>(out + base);
        p[0] = make_float4(a12[0], a12[1], a12[2],  a12[3]);
        p[1] = make_float4(a12[4], a12[5], a12[6],  a12[7]);
        p[2] = make_float4(a12[8], a12[9], a12[10], a12[11]);

        if (offdiag) {
            #pragma unroll
            for (int jj = 0; jj < 4; jj++) {
                int jr = jq*16 + q*4 + jj;
                #pragma unroll
                for (int c = 0; c < NCH; c++)
                    sM[jr*KB_MSTR + i_loc*NCH + c] = a12[jj*NCH + c];
            }
        }
    }

    if (offdiag) {
        __syncthreads();
        // mirror: 64 j-rows x 48 float4, coalesced
        #pragma unroll 4
        for (int f = t; f < 64*48; f += 256) {
            int r  = f / 48;
            int c4 = f - r*48;
            int s0 = r*KB_MSTR + c4*4;
            float4 v = *reinterpret_cast<const float4*>(&sM[s0]);
            reinterpret_cast<float4*>(
                out + ((size_t)(b*ND + tJ*64 + r)*ND + tI*64) * NCH)[c4] = v;
        }
    }
}

// ---------------------------------------------------------------------------
extern "C" void kernel_launch(void* const* d_in, const int* in_sizes, int n_in,
                              void* d_out, int out_size)
{
    const float* xc      = (const float*)d_in[0];
    const float* yc      = (const float*)d_in[1];
    const float* mu      = (const float*)d_in[2];
    const float* inv_std = (const float*)d_in[3];
    const float* likerr  = (const float*)d_in[4];
    const float* unif    = (const float*)d_in[5];
    const float* W1 = (const float*)d_in[6];  const float* b1 = (const float*)d_in[7];
    const float* W2 = (const float*)d_in[8];  const float* b2 = (const float*)d_in[9];
    const float* W3 = (const float*)d_in[10]; const float* b3 = (const float*)d_in[11];
    const float* W4 = (const float*)d_in[12]; const float* b4 = (const float*)d_in[13];
    const float* W5 = (const float*)d_in[14]; const float* b5 = (const float*)d_in[15];
    float* out = (float*)d_out;

    cudaFuncSetAttribute(kB_out, cudaFuncAttributeMaxDynamicSharedMemorySize, KB_TOT_B);

    kA_feat <<< dim3(3, ND/64, NB*NCH), 256 >>>(xc, yc, mu, inv_std);
    k34_hmean_mlp <<< NB*NCH, 256 >>>(yc, W1, b1, W2, b2, W3, b3, W4, b4, W5, b5, unif);
    kB_out  <<< dim3(ND/64, ND/64, NB), 256, KB_TOT_B >>>(out, xc, mu, inv_std, likerr);
}